// round 16
// baseline (speedup 1.0000x reference)
#include <cuda_runtime.h>

// Problem constants
#define HW    115200      // 240*480
#define HW4   28800       // HW/4
#define C_    128
#define L_    4
#define R_    8
#define KK    36
#define CH    64
#define WF    (C_*R_ + R_*KK)   // 1312

// Scratch (allocation-free: __device__ globals)
__device__ float g_ctx[L_*C_];
__device__ float g_W1[L_*C_*R_];          // pre-scaled by gain[c]
__device__ float g_W2[L_*R_*KK];

// -------------------------------------------------------------------------
// K1: ctx[l,c] = mean over HW of x[l,c,:,:].  512 blocks x 256 threads.
// (Proven ~39us @ 78% DRAM — at achieved roofline. FROZEN.)
// -------------------------------------------------------------------------
__global__ void __launch_bounds__(256)
mean_kernel(const float* __restrict__ x) {
    const int lc = blockIdx.x;
    const float4* xp = reinterpret_cast<const float4*>(x + (size_t)lc * HW);
    float s = 0.f;
    for (int i = threadIdx.x; i < HW4; i += 256) {
        float4 v = xp[i];
        s += (v.x + v.y) + (v.z + v.w);
    }
    __shared__ float red[8];
    #pragma unroll
    for (int o = 16; o; o >>= 1) s += __shfl_down_sync(0xffffffffu, s, o);
    if ((threadIdx.x & 31) == 0) red[threadIdx.x >> 5] = s;
    __syncthreads();
    if (threadIdx.x < 8) {
        s = red[threadIdx.x];
        #pragma unroll
        for (int o = 4; o; o >>= 1) s += __shfl_down_sync(0xffu, s, o);
        if (threadIdx.x == 0) g_ctx[lc] = s * (1.0f / (float)HW);
    }
}

// -------------------------------------------------------------------------
// K2: full hypernet. 21 blocks x 256 threads (proven ~2us. FROZEN.)
// -------------------------------------------------------------------------
__global__ void __launch_bounds__(256)
hyper_kernel(const float* __restrict__ Wa, const float* __restrict__ ba,
             const float* __restrict__ Wb, const float* __restrict__ bb,
             const float* __restrict__ gain) {
    __shared__ float ctx_s[L_*C_];
    __shared__ float h_s[L_*CH];
    const int tid = threadIdx.x;

    for (int i = tid; i < L_*C_; i += 256) ctx_s[i] = g_ctx[i];
    __syncthreads();

    {   // h: 256 threads == 4*64 outputs
        const int l = tid / CH, j = tid % CH;
        float acc = ba[j];
        #pragma unroll 8
        for (int c = 0; c < C_; c++) acc += ctx_s[l*C_ + c] * Wa[c*CH + j];
        float sg = 1.f / (1.f + expf(-acc));
        h_s[l*CH + j] = acc * sg;
    }
    __syncthreads();

    const int idx = blockIdx.x * 256 + tid;
    if (idx >= L_*WF) return;
    const int l = idx / WF, o = idx % WF;
    float acc = bb[o];
    #pragma unroll 8
    for (int j = 0; j < CH; j++) acc += h_s[l*CH + j] * Wb[j*WF + o];
    if (o < C_*R_) g_W1[l*C_*R_ + o] = acc * gain[o / R_];
    else           g_W2[l*R_*KK + (o - C_*R_)] = acc;
}

// -------------------------------------------------------------------------
// K3: out = x + (gain*W1) @ (W2 @ Y), fused. R5's proven body (z in regs,
// 9x4 prologue chunks, 8-batched c-loop / MLP=8), relaunched as 512-thread
// blocks: grid (57, 4) = 228 blocks <= 296 occ-2 slots -> SINGLE WAVE,
// no solo-block tail (the ~20us slack in R5).
// -------------------------------------------------------------------------
__global__ void __launch_bounds__(512, 2)
apply_kernel(const float* __restrict__ x,
             const float* __restrict__ Y,
             float* __restrict__ out) {
    const int l = blockIdx.y;
    const int tid = threadIdx.x;

    __shared__ float w1s[C_*R_];
    __shared__ float w2s[R_*KK];
    for (int i = tid; i < C_*R_; i += 512) w1s[i] = g_W1[l*C_*R_ + i];
    for (int i = tid; i < R_*KK; i += 512) w2s[i] = g_W2[l*R_*KK + i];
    __syncthreads();

    const int p4 = blockIdx.x * 512 + tid;
    if (p4 >= HW4) return;

    // --- prologue: z[r] = sum_k w2s[r,k] * Y[k,p] (in registers) ---
    const float4* Y4 = reinterpret_cast<const float4*>(Y);
    float4 z[R_];
    #pragma unroll
    for (int r = 0; r < R_; r++) z[r] = make_float4(0.f, 0.f, 0.f, 0.f);

    for (int kc = 0; kc < KK; kc += 4) {          // 9 chunks x 4 loads
        float4 y[4];
        #pragma unroll
        for (int j = 0; j < 4; j++)
            y[j] = Y4[(size_t)(kc + j) * HW4 + p4];
        #pragma unroll
        for (int j = 0; j < 4; j++) {
            #pragma unroll
            for (int r = 0; r < R_; r++) {
                float w = w2s[r*KK + kc + j];
                z[r].x = fmaf(w, y[j].x, z[r].x);
                z[r].y = fmaf(w, y[j].y, z[r].y);
                z[r].z = fmaf(w, y[j].z, z[r].z);
                z[r].w = fmaf(w, y[j].w, z[r].w);
            }
        }
    }

    // --- c-loop: 8 front-batched x loads (MLP=8) ---
    const float4* x4 = reinterpret_cast<const float4*>(x);
    float4*       o4 = reinterpret_cast<float4*>(out);
    const size_t base = (size_t)l * C_ * HW4 + p4;

    for (int cc = 0; cc < C_; cc += 8) {
        float4 xv[8];
        #pragma unroll
        for (int j = 0; j < 8; j++)
            xv[j] = x4[base + (size_t)(cc + j) * HW4];
        #pragma unroll
        for (int j = 0; j < 8; j++) {
            float4 acc = make_float4(0.f, 0.f, 0.f, 0.f);
            const int c = cc + j;
            #pragma unroll
            for (int r = 0; r < R_; r++) {
                float w = w1s[c*R_ + r];
                acc.x = fmaf(w, z[r].x, acc.x);
                acc.y = fmaf(w, z[r].y, acc.y);
                acc.z = fmaf(w, z[r].z, acc.z);
                acc.w = fmaf(w, z[r].w, acc.w);
            }
            xv[j].x += acc.x;
            xv[j].y += acc.y;
            xv[j].z += acc.z;
            xv[j].w += acc.w;
            o4[base + (size_t)c * HW4] = xv[j];
        }
    }
}

// -------------------------------------------------------------------------
// launch.  Inputs (metadata order): x, Wa, ba, Wb, bb, gain, Y  (all f32)
// -------------------------------------------------------------------------
extern "C" void kernel_launch(void* const* d_in, const int* in_sizes, int n_in,
                              void* d_out, int out_size) {
    const float* x    = (const float*)d_in[0];
    const float* Wa   = (const float*)d_in[1];
    const float* ba   = (const float*)d_in[2];
    const float* Wb   = (const float*)d_in[3];
    const float* bb   = (const float*)d_in[4];
    const float* gain = (const float*)d_in[5];
    const float* Y    = (const float*)d_in[6];
    float* out = (float*)d_out;

    mean_kernel<<<L_*C_, 256>>>(x);
    hyper_kernel<<<(L_*WF + 255)/256, 256>>>(Wa, ba, Wb, bb, gain);
    apply_kernel<<<dim3((HW4 + 511)/512, L_), 512>>>(x, Y, out);
}